// round 3
// baseline (speedup 1.0000x reference)
#include <cuda_runtime.h>
#include <math.h>

constexpr int Bn   = 64;
constexpr int Hn   = 512;
constexpr int Wn   = 512;
constexpr int NPTS = 512;
constexpr int HWn  = Hn * Wn;
constexpr int SLICES = 16;                 // reduce blocks per image
constexpr int RB = Bn * SLICES;            // 1024 reduce blocks
constexpr int TSLOTS = 5888;               // hash slots (>= 4608 max entries)
constexpr float SCALE = 0.25f;             // 512/2048
constexpr double CELL_AREA = 16.0;

// zero-initialized accumulators; reset inside finalize for graph replay
__device__ double g_S[Bn], g_Q[Bn], g_T[Bn], g_A[Bn], g_C[Bn];
__device__ unsigned g_done;

__global__ void __launch_bounds__(256)
k_fused(const float* __restrict__ pred,
        const float* __restrict__ points,
        float* __restrict__ out) {
    __shared__ int    s_key[TSLOTS];
    __shared__ float  s_val[TSLOTS];
    __shared__ double s_red[24];           // 8 warps x 3 doubles
    const int tid = threadIdx.x;

    if (blockIdx.x < Bn) {
        // ---------- sparse-target block: one image ----------
        const int b = blockIdx.x;
        for (int i = tid; i < TSLOTS; i += 256) { s_key[i] = -1; s_val[i] = 0.f; }
        __syncthreads();

        double Tl = 0.0;
        #pragma unroll
        for (int pp = 0; pp < 2; ++pp) {
            int pt = pp * 256 + tid;       // 512 points / 256 threads
            float px = points[((size_t)b * NPTS + pt) * 2 + 0];
            float py = points[((size_t)b * NPTS + pt) * 2 + 1];
            int x = (int)fminf(fmaxf(px * SCALE, 0.f), (float)(Wn - 1));
            int y = (int)fminf(fmaxf(py * SCALE, 0.f), (float)(Hn - 1));
            #pragma unroll
            for (int dy = -1; dy <= 1; ++dy)
                #pragma unroll
                for (int dx = -1; dx <= 1; ++dx) {
                    int ny = y + dy, nx = x + dx;
                    if ((unsigned)ny < (unsigned)Hn && (unsigned)nx < (unsigned)Wn) {
                        int r2 = dy * dy + dx * dx;
                        float w = r2 == 0 ? 1.0f
                                : (r2 == 1 ? 0.60653066f : 0.49306869f);
                        int key = ny * Wn + nx;
                        unsigned h = (unsigned)key * 2654435761u;
                        int slot = (int)(((unsigned long long)h * TSLOTS) >> 32);
                        for (;;) {
                            int k = atomicCAS(&s_key[slot], -1, key);
                            if (k == -1 || k == key) {
                                atomicAdd(&s_val[slot], w);
                                break;
                            }
                            if (++slot == TSLOTS) slot = 0;
                        }
                        Tl += (double)w;
                    }
                }
        }
        __syncthreads();

        // scan table: T already have; A = sum t*pred, C = sum t^2
        const float* pb = pred + (size_t)b * HWn;
        double Al = 0.0, Cl = 0.0;
        for (int i = tid; i < TSLOTS; i += 256) {
            int k = s_key[i];
            if (k >= 0) {
                float t = s_val[i];
                Cl += (double)t * (double)t;
                Al += (double)t * (double)__ldg(&pb[k]);
            }
        }
        // block reduce (T, A, C)
        #pragma unroll
        for (int o = 16; o; o >>= 1) {
            Tl += __shfl_down_sync(0xffffffffu, Tl, o);
            Al += __shfl_down_sync(0xffffffffu, Al, o);
            Cl += __shfl_down_sync(0xffffffffu, Cl, o);
        }
        int lane = tid & 31, wid = tid >> 5;
        if (lane == 0) { s_red[wid] = Tl; s_red[8 + wid] = Al; s_red[16 + wid] = Cl; }
        __syncthreads();
        if (wid == 0) {
            Tl = (lane < 8) ? s_red[lane] : 0.0;
            Al = (lane < 8) ? s_red[8 + lane] : 0.0;
            Cl = (lane < 8) ? s_red[16 + lane] : 0.0;
            #pragma unroll
            for (int o = 4; o; o >>= 1) {
                Tl += __shfl_down_sync(0xffffffffu, Tl, o);
                Al += __shfl_down_sync(0xffffffffu, Al, o);
                Cl += __shfl_down_sync(0xffffffffu, Cl, o);
            }
            if (lane == 0) { g_T[b] = Tl; g_A[b] = Al; g_C[b] = Cl; }
        }
    } else {
        // ---------- streaming reduce block: S, Q over one slice ----------
        int rb = blockIdx.x - Bn;
        int b = rb >> 4, slice = rb & (SLICES - 1);
        constexpr int CH = HWn / 4 / SLICES;   // 4096 float4 per block
        const float4* p = reinterpret_cast<const float4*>(pred)
                          + (size_t)b * (HWn / 4) + (size_t)slice * CH;
        float s = 0.f, q = 0.f;
        #pragma unroll 4
        for (int i = tid; i < CH; i += 256) {
            float4 v = p[i];
            s += (v.x + v.y) + (v.z + v.w);
            q += v.x * v.x + v.y * v.y + v.z * v.z + v.w * v.w;
        }
        #pragma unroll
        for (int o = 16; o; o >>= 1) {
            s += __shfl_down_sync(0xffffffffu, s, o);
            q += __shfl_down_sync(0xffffffffu, q, o);
        }
        int lane = tid & 31, wid = tid >> 5;
        if (lane == 0) { s_red[wid] = (double)s; s_red[8 + wid] = (double)q; }
        __syncthreads();
        if (wid == 0) {
            double sd = (lane < 8) ? s_red[lane] : 0.0;
            double qd = (lane < 8) ? s_red[8 + lane] : 0.0;
            #pragma unroll
            for (int o = 4; o; o >>= 1) {
                sd += __shfl_down_sync(0xffffffffu, sd, o);
                qd += __shfl_down_sync(0xffffffffu, qd, o);
            }
            if (lane == 0) {
                atomicAdd(&g_S[b], sd);
                atomicAdd(&g_Q[b], qd);
            }
        }
    }

    // ---------- last-block-done: finalize + reset ----------
    __shared__ int is_last;
    __threadfence();
    __syncthreads();
    if (tid == 0) {
        unsigned r = atomicAdd(&g_done, 1u);
        is_last = (r == gridDim.x - 1) ? 1 : 0;
    }
    __syncthreads();
    if (!is_last) return;

    double cnt = 0.0, sp = 0.0;
    if (tid < Bn) {
        double S = g_S[tid];
        cnt = fabs(S / CELL_AREA - (double)NPTS);
        double Sp = S + 1e-8;
        double T = g_T[tid];
        sp = (g_Q[tid] / (Sp * Sp) - 2.0 * g_A[tid] / (Sp * T) + g_C[tid] / (T * T))
             / (double)HWn;
        g_S[tid] = 0.0; g_Q[tid] = 0.0;     // reset for next graph replay
    }
    #pragma unroll
    for (int o = 16; o; o >>= 1) {
        cnt += __shfl_down_sync(0xffffffffu, cnt, o);
        sp  += __shfl_down_sync(0xffffffffu, sp, o);
    }
    __syncthreads();                         // reuse s_red safely
    int lane = tid & 31, wid = tid >> 5;
    if (wid < 2 && lane == 0) { s_red[wid] = cnt; s_red[8 + wid] = sp; }
    __syncthreads();
    if (tid == 0) {
        g_done = 0u;
        double count_loss = (s_red[0] + s_red[1]) / (double)Bn;
        double spatial    = (s_red[8] + s_red[9]) / (double)Bn;
        out[0] = (float)(2.5 * count_loss + 0.1 * spatial);
        out[1] = (float)count_loss;
        out[2] = (float)spatial;
    }
}

extern "C" void kernel_launch(void* const* d_in, const int* in_sizes, int n_in,
                              void* d_out, int out_size) {
    const float* pred   = (const float*)d_in[0];
    const float* points = (const float*)d_in[1];
    float* out = (float*)d_out;
    k_fused<<<Bn + RB, 256>>>(pred, points, out);
}

// round 4
// speedup vs baseline: 5.8082x; 5.8082x over previous
#include <cuda_runtime.h>
#include <math.h>

constexpr int Bn   = 64;
constexpr int Hn   = 512;
constexpr int Wn   = 512;
constexpr int NPTS = 512;
constexpr int HWn  = Hn * Wn;
constexpr int SLICES = 16;                 // streaming blocks per image
constexpr int RB = Bn * SLICES;            // 1024 streaming blocks
constexpr int NTAP = Bn * NPTS * 9;        // 294912 point-taps
constexpr int TB = NTAP / 256;             // 1152 tap blocks
constexpr float SCALE = 0.25f;             // 512/2048
constexpr double CELL_AREA = 16.0;

// zero-initialized device scratch; restored every call for graph replay
__device__ float  g_target[(size_t)Bn * HWn];   // sparse target grid
__device__ double g_S[Bn], g_Q[Bn], g_T[Bn], g_A[Bn], g_C[Bn];
__device__ unsigned g_done;

// tap index u -> (image b, cell idx or -1, weight w)
__device__ __forceinline__ void tap_decode(const float* __restrict__ points,
                                           int u, int& b, int& idx, float& w) {
    int pt  = u / 9;
    int tap = u - pt * 9;
    b = pt >> 9;                            // pt / NPTS
    float px = __ldg(&points[2 * pt + 0]);
    float py = __ldg(&points[2 * pt + 1]);
    int x = (int)fminf(fmaxf(px * SCALE, 0.f), (float)(Wn - 1));
    int y = (int)fminf(fmaxf(py * SCALE, 0.f), (float)(Hn - 1));
    int dy = tap / 3 - 1;
    int dx = tap - (tap / 3) * 3 - 1;
    int ny = y + dy, nx = x + dx;
    if ((unsigned)ny < (unsigned)Hn && (unsigned)nx < (unsigned)Wn) {
        int r2 = dy * dy + dx * dx;
        w = (r2 == 0) ? 1.0f : (r2 == 1 ? 0.60653066f : 0.49306869f);
        idx = b * HWn + ny * Wn + nx;
    } else { idx = -1; w = 0.f; }
}

// K1: tap blocks [0,TB): scatter target, accumulate T, A, C (via atomic
//     return telescoping). streaming blocks [TB,TB+RB): S, Q over pred.
__global__ void __launch_bounds__(256)
k_main(const float* __restrict__ pred, const float* __restrict__ points) {
    const int tid = threadIdx.x;
    if (blockIdx.x < TB) {
        int u = blockIdx.x * 256 + tid;
        int b, idx; float w;
        tap_decode(points, u, b, idx, w);
        float a = 0.f, c = 0.f;
        if (idx >= 0) {
            float old = atomicAdd(&g_target[idx], w);   // returns prior value
            c = w * (2.f * old + w);                    // (old+w)^2 - old^2
            a = w * __ldg(&pred[idx]);
        }
        // 4608 taps per image and 4608 % 32 == 0 -> warp never straddles b
        double td = (double)w, ad = (double)a, cd = (double)c;
        #pragma unroll
        for (int o = 16; o; o >>= 1) {
            td += __shfl_down_sync(0xffffffffu, td, o);
            ad += __shfl_down_sync(0xffffffffu, ad, o);
            cd += __shfl_down_sync(0xffffffffu, cd, o);
        }
        if ((tid & 31) == 0) {
            atomicAdd(&g_T[b], td);
            atomicAdd(&g_A[b], ad);
            atomicAdd(&g_C[b], cd);
        }
    } else {
        int rb = blockIdx.x - TB;
        int b = rb >> 4, slice = rb & (SLICES - 1);
        constexpr int CH = HWn / 4 / SLICES;   // 4096 float4 per block
        const float4* p = reinterpret_cast<const float4*>(pred)
                          + (size_t)b * (HWn / 4) + (size_t)slice * CH;
        float s = 0.f, q = 0.f;
        #pragma unroll 4
        for (int i = tid; i < CH; i += 256) {
            float4 v = p[i];
            s += (v.x + v.y) + (v.z + v.w);
            q += v.x * v.x + v.y * v.y + v.z * v.z + v.w * v.w;
        }
        #pragma unroll
        for (int o = 16; o; o >>= 1) {
            s += __shfl_down_sync(0xffffffffu, s, o);
            q += __shfl_down_sync(0xffffffffu, q, o);
        }
        __shared__ float ss[8], sq[8];
        int lane = tid & 31, wid = tid >> 5;
        if (lane == 0) { ss[wid] = s; sq[wid] = q; }
        __syncthreads();
        if (wid == 0) {
            s = (lane < 8) ? ss[lane] : 0.f;
            q = (lane < 8) ? sq[lane] : 0.f;
            #pragma unroll
            for (int o = 4; o; o >>= 1) {
                s += __shfl_down_sync(0xffffffffu, s, o);
                q += __shfl_down_sync(0xffffffffu, q, o);
            }
            if (lane == 0) {
                atomicAdd(&g_S[b], (double)s);
                atomicAdd(&g_Q[b], (double)q);
            }
        }
    }
}

// K2: clean touched cells (plain stores), then last block finalizes + resets.
__global__ void __launch_bounds__(256)
k_tail(const float* __restrict__ points, float* __restrict__ out) {
    const int tid = threadIdx.x;
    int u = blockIdx.x * 256 + tid;
    int b, idx; float w;
    tap_decode(points, u, b, idx, w);
    if (idx >= 0) g_target[idx] = 0.f;      // redundant stores are fine

    __shared__ int is_last;
    __threadfence();
    __syncthreads();
    if (tid == 0) {
        unsigned r = atomicAdd(&g_done, 1u);
        is_last = (r == (unsigned)gridDim.x - 1u) ? 1 : 0;
    }
    __syncthreads();
    if (!is_last) return;

    double cnt = 0.0, sp = 0.0;
    if (tid < Bn) {
        double S = g_S[tid];
        cnt = fabs(S / CELL_AREA - (double)NPTS);
        double Sp = S + 1e-8;
        double T = g_T[tid];
        sp = (g_Q[tid] / (Sp * Sp) - 2.0 * g_A[tid] / (Sp * T) + g_C[tid] / (T * T))
             / (double)HWn;
        // reset accumulators for graph replay
        g_S[tid] = 0.0; g_Q[tid] = 0.0; g_T[tid] = 0.0;
        g_A[tid] = 0.0; g_C[tid] = 0.0;
    }
    #pragma unroll
    for (int o = 16; o; o >>= 1) {
        cnt += __shfl_down_sync(0xffffffffu, cnt, o);
        sp  += __shfl_down_sync(0xffffffffu, sp, o);
    }
    __shared__ double sc[2], ssp[2];
    int lane = tid & 31, wid = tid >> 5;
    if (wid < 2 && lane == 0) { sc[wid] = cnt; ssp[wid] = sp; }
    __syncthreads();
    if (tid == 0) {
        g_done = 0u;
        double count_loss = (sc[0] + sc[1]) / (double)Bn;
        double spatial    = (ssp[0] + ssp[1]) / (double)Bn;
        out[0] = (float)(2.5 * count_loss + 0.1 * spatial);
        out[1] = (float)count_loss;
        out[2] = (float)spatial;
    }
}

extern "C" void kernel_launch(void* const* d_in, const int* in_sizes, int n_in,
                              void* d_out, int out_size) {
    const float* pred   = (const float*)d_in[0];
    const float* points = (const float*)d_in[1];
    float* out = (float*)d_out;
    k_main<<<TB + RB, 256>>>(pred, points);
    k_tail<<<TB, 256>>>(points, out);
}

// round 5
// speedup vs baseline: 6.8750x; 1.1837x over previous
#include <cuda_runtime.h>
#include <math.h>

constexpr int Bn   = 64;
constexpr int Hn   = 512;
constexpr int Wn   = 512;
constexpr int NPTS = 512;
constexpr int HWn  = Hn * Wn;
constexpr int SLICES = 16;                 // streaming blocks per image
constexpr int RB = Bn * SLICES;            // 1024 streaming blocks
constexpr int NTAP = Bn * NPTS * 9;        // 294912 taps
constexpr int TB = NTAP / 256;             // 1152 tap blocks
constexpr int PB = (Bn * NPTS) / 256;      // 128 point blocks (cleanup)
constexpr float SCALE = 0.25f;             // 512/2048
constexpr double CELL_AREA = 16.0;

// zero-initialized device scratch; restored every call for graph replay
__device__ float  g_target[(size_t)Bn * HWn];
__device__ double g_S[Bn], g_Q[Bn], g_T[Bn], g_A[Bn], g_C[Bn];

__device__ __forceinline__ void tap_decode(const float* __restrict__ points,
                                           int u, int& b, int& idx, float& w) {
    int pt  = u / 9;
    int tap = u - pt * 9;
    b = pt >> 9;                            // pt / NPTS
    float px = __ldg(&points[2 * pt + 0]);
    float py = __ldg(&points[2 * pt + 1]);
    int x = (int)fminf(fmaxf(px * SCALE, 0.f), (float)(Wn - 1));
    int y = (int)fminf(fmaxf(py * SCALE, 0.f), (float)(Hn - 1));
    int dy = tap / 3 - 1;
    int dx = tap - (tap / 3) * 3 - 1;
    int ny = y + dy, nx = x + dx;
    if ((unsigned)ny < (unsigned)Hn && (unsigned)nx < (unsigned)Wn) {
        int r2 = dy * dy + dx * dx;
        w = (r2 == 0) ? 1.0f : (r2 == 1 ? 0.60653066f : 0.49306869f);
        idx = b * HWn + ny * Wn + nx;
    } else { idx = -1; w = 0.f; }
}

// K1: blocks [0,RB) stream S,Q; blocks [RB,RB+TB) scatter (non-returning
//     atomics), accumulate T and A = sum w*pred[cell].
__global__ void __launch_bounds__(256)
k_main(const float* __restrict__ pred, const float* __restrict__ points) {
    const int tid = threadIdx.x;
    if (blockIdx.x < RB) {
        int b = blockIdx.x >> 4, slice = blockIdx.x & (SLICES - 1);
        constexpr int CH = HWn / 4 / SLICES;   // 4096 float4 per block
        const float4* p = reinterpret_cast<const float4*>(pred)
                          + (size_t)b * (HWn / 4) + (size_t)slice * CH;
        float s = 0.f, q = 0.f;
        #pragma unroll 4
        for (int i = tid; i < CH; i += 256) {
            float4 v = p[i];
            s += (v.x + v.y) + (v.z + v.w);
            q += v.x * v.x + v.y * v.y + v.z * v.z + v.w * v.w;
        }
        #pragma unroll
        for (int o = 16; o; o >>= 1) {
            s += __shfl_down_sync(0xffffffffu, s, o);
            q += __shfl_down_sync(0xffffffffu, q, o);
        }
        __shared__ float ss[8], sq[8];
        int lane = tid & 31, wid = tid >> 5;
        if (lane == 0) { ss[wid] = s; sq[wid] = q; }
        __syncthreads();
        if (wid == 0) {
            s = (lane < 8) ? ss[lane] : 0.f;
            q = (lane < 8) ? sq[lane] : 0.f;
            #pragma unroll
            for (int o = 4; o; o >>= 1) {
                s += __shfl_down_sync(0xffffffffu, s, o);
                q += __shfl_down_sync(0xffffffffu, q, o);
            }
            if (lane == 0) {
                atomicAdd(&g_S[b], (double)s);
                atomicAdd(&g_Q[b], (double)q);
            }
        }
    } else {
        int u = (blockIdx.x - RB) * 256 + tid;
        int b, idx; float w;
        tap_decode(points, u, b, idx, w);
        float a = 0.f;
        if (idx >= 0) {
            atomicAdd(&g_target[idx], w);       // no return -> REDG
            a = w * __ldg(&pred[idx]);
        }
        // 4608 taps per image, 4608 % 32 == 0 -> warps never straddle b
        #pragma unroll
        for (int o = 16; o; o >>= 1) {
            w += __shfl_down_sync(0xffffffffu, w, o);
            a += __shfl_down_sync(0xffffffffu, a, o);
        }
        if ((tid & 31) == 0) {
            atomicAdd(&g_T[b], (double)w);
            atomicAdd(&g_A[b], (double)a);
        }
    }
}

// K2: plain-load gather: C = sum_taps w * t[cell]  (== sum_cells t^2).
__global__ void __launch_bounds__(256)
k_gatherC(const float* __restrict__ points) {
    const int tid = threadIdx.x;
    int u = blockIdx.x * 256 + tid;
    int b, idx; float w;
    tap_decode(points, u, b, idx, w);
    float c = (idx >= 0) ? w * g_target[idx] : 0.f;
    #pragma unroll
    for (int o = 16; o; o >>= 1) c += __shfl_down_sync(0xffffffffu, c, o);
    if ((tid & 31) == 0) atomicAdd(&g_C[b], (double)c);
}

// K3: blocks [0,PB) zero the touched cells (plain stores, one point/thread);
//     block PB finalizes (safe: K2 completed via stream ordering) + resets.
__global__ void __launch_bounds__(256)
k_tail(const float* __restrict__ points, float* __restrict__ out) {
    const int tid = threadIdx.x;
    if (blockIdx.x < PB) {
        int pt = blockIdx.x * 256 + tid;
        int b = pt >> 9;
        float px = __ldg(&points[2 * pt + 0]);
        float py = __ldg(&points[2 * pt + 1]);
        int x = (int)fminf(fmaxf(px * SCALE, 0.f), (float)(Wn - 1));
        int y = (int)fminf(fmaxf(py * SCALE, 0.f), (float)(Hn - 1));
        float* tg = g_target + (size_t)b * HWn;
        #pragma unroll
        for (int dy = -1; dy <= 1; ++dy) {
            int ny = y + dy;
            if ((unsigned)ny >= (unsigned)Hn) continue;
            #pragma unroll
            for (int dx = -1; dx <= 1; ++dx) {
                int nx = x + dx;
                if ((unsigned)nx < (unsigned)Wn) tg[ny * Wn + nx] = 0.f;
            }
        }
        return;
    }

    // finalize block
    double cnt = 0.0, sp = 0.0;
    if (tid < Bn) {
        double S = g_S[tid];
        cnt = fabs(S / CELL_AREA - (double)NPTS);
        double Sp = S + 1e-8;
        double T = g_T[tid];
        sp = (g_Q[tid] / (Sp * Sp) - 2.0 * g_A[tid] / (Sp * T) + g_C[tid] / (T * T))
             / (double)HWn;
        g_S[tid] = 0.0; g_Q[tid] = 0.0; g_T[tid] = 0.0;
        g_A[tid] = 0.0; g_C[tid] = 0.0;
    }
    #pragma unroll
    for (int o = 16; o; o >>= 1) {
        cnt += __shfl_down_sync(0xffffffffu, cnt, o);
        sp  += __shfl_down_sync(0xffffffffu, sp, o);
    }
    __shared__ double sc[2], ssp[2];
    int lane = tid & 31, wid = tid >> 5;
    if (wid < 2 && lane == 0) { sc[wid] = cnt; ssp[wid] = sp; }
    __syncthreads();
    if (tid == 0) {
        double count_loss = (sc[0] + sc[1]) / (double)Bn;
        double spatial    = (ssp[0] + ssp[1]) / (double)Bn;
        out[0] = (float)(2.5 * count_loss + 0.1 * spatial);
        out[1] = (float)count_loss;
        out[2] = (float)spatial;
    }
}

extern "C" void kernel_launch(void* const* d_in, const int* in_sizes, int n_in,
                              void* d_out, int out_size) {
    const float* pred   = (const float*)d_in[0];
    const float* points = (const float*)d_in[1];
    float* out = (float*)d_out;
    k_main<<<RB + TB, 256>>>(pred, points);
    k_gatherC<<<TB, 256>>>(points);
    k_tail<<<PB + 1, 256>>>(points, out);
}

// round 6
// speedup vs baseline: 7.3234x; 1.0652x over previous
#include <cuda_runtime.h>
#include <math.h>

constexpr int Bn   = 64;
constexpr int Hn   = 512;
constexpr int Wn   = 512;
constexpr int NPTS = 512;
constexpr int HWn  = Hn * Wn;
constexpr int SLICES = 16;                 // streaming blocks per image
constexpr int RB = Bn * SLICES;            // 1024 streaming blocks (1 wave)
constexpr int NTAP = Bn * NPTS * 9;        // 294912 taps
constexpr int TB = NTAP / 256;             // 1152 tap blocks
constexpr int PB = (Bn * NPTS) / 256;      // 128 cleanup blocks
constexpr float SCALE = 0.25f;             // 512/2048
constexpr double CELL_AREA = 16.0;

// zero-initialized device scratch; restored every call for graph replay
__device__ float  g_target[(size_t)Bn * HWn];
__device__ double g_S[Bn], g_Q[Bn], g_T[Bn], g_A[Bn], g_C[Bn];

// ---------------- K1: pure streaming reduce (S, Q) ----------------
__global__ void __launch_bounds__(256)
k_reduce(const float* __restrict__ pred) {
    const int tid = threadIdx.x;
    int b = blockIdx.x >> 4, slice = blockIdx.x & (SLICES - 1);
    constexpr int CH = HWn / 4 / SLICES;   // 4096 float4 per block
    const float4* p = reinterpret_cast<const float4*>(pred)
                      + (size_t)b * (HWn / 4) + (size_t)slice * CH;
    float s = 0.f, q = 0.f;
    // 16 float4 per thread: 2 outer iters x 8 batched loads (MLP ~8)
    #pragma unroll
    for (int it = 0; it < 2; ++it) {
        float4 v[8];
        #pragma unroll
        for (int j = 0; j < 8; ++j)
            v[j] = p[(it * 8 + j) * 256 + tid];
        #pragma unroll
        for (int j = 0; j < 8; ++j) {
            s += (v[j].x + v[j].y) + (v[j].z + v[j].w);
            q += v[j].x * v[j].x + v[j].y * v[j].y
               + v[j].z * v[j].z + v[j].w * v[j].w;
        }
    }
    #pragma unroll
    for (int o = 16; o; o >>= 1) {
        s += __shfl_down_sync(0xffffffffu, s, o);
        q += __shfl_down_sync(0xffffffffu, q, o);
    }
    __shared__ float ss[8], sq[8];
    int lane = tid & 31, wid = tid >> 5;
    if (lane == 0) { ss[wid] = s; sq[wid] = q; }
    __syncthreads();
    if (wid == 0) {
        s = (lane < 8) ? ss[lane] : 0.f;
        q = (lane < 8) ? sq[lane] : 0.f;
        #pragma unroll
        for (int o = 4; o; o >>= 1) {
            s += __shfl_down_sync(0xffffffffu, s, o);
            q += __shfl_down_sync(0xffffffffu, q, o);
        }
        if (lane == 0) {
            atomicAdd(&g_S[b], (double)s);
            atomicAdd(&g_Q[b], (double)q);
        }
    }
}

// ---------------- K2: taps — scatter + T + A + C (telescoping) ----
__global__ void __launch_bounds__(256)
k_taps(const float* __restrict__ pred, const float* __restrict__ points) {
    const int tid = threadIdx.x;
    int u = blockIdx.x * 256 + tid;
    int pt  = u / 9;
    int tap = u - pt * 9;
    int b = pt >> 9;                        // pt / NPTS
    float px = __ldg(&points[2 * pt + 0]);
    float py = __ldg(&points[2 * pt + 1]);
    int x = (int)fminf(fmaxf(px * SCALE, 0.f), (float)(Wn - 1));
    int y = (int)fminf(fmaxf(py * SCALE, 0.f), (float)(Hn - 1));
    int dy = tap / 3 - 1;
    int dx = tap - (tap / 3) * 3 - 1;
    int ny = y + dy, nx = x + dx;

    float w = 0.f, a = 0.f, c = 0.f;
    if ((unsigned)ny < (unsigned)Hn && (unsigned)nx < (unsigned)Wn) {
        int r2 = dy * dy + dx * dx;
        w = (r2 == 0) ? 1.0f : (r2 == 1 ? 0.60653066f : 0.49306869f);
        int idx = b * HWn + ny * Wn + nx;
        float old = atomicAdd(&g_target[idx], w);    // returning atomic
        c = w * (2.f * old + w);                     // (old+w)^2 - old^2
        a = w * __ldg(&pred[idx]);                   // L2-warm after K1
    }
    // 4608 taps per image, 4608 % 32 == 0 -> warps never straddle b
    #pragma unroll
    for (int o = 16; o; o >>= 1) {
        w += __shfl_down_sync(0xffffffffu, w, o);
        a += __shfl_down_sync(0xffffffffu, a, o);
        c += __shfl_down_sync(0xffffffffu, c, o);
    }
    if ((tid & 31) == 0) {
        atomicAdd(&g_T[b], (double)w);
        atomicAdd(&g_A[b], (double)a);
        atomicAdd(&g_C[b], (double)c);
    }
}

// ---------------- K3: clean touched cells + finalize --------------
__global__ void __launch_bounds__(256)
k_tail(const float* __restrict__ points, float* __restrict__ out) {
    const int tid = threadIdx.x;
    if (blockIdx.x < PB) {
        int pt = blockIdx.x * 256 + tid;
        int b = pt >> 9;
        float px = __ldg(&points[2 * pt + 0]);
        float py = __ldg(&points[2 * pt + 1]);
        int x = (int)fminf(fmaxf(px * SCALE, 0.f), (float)(Wn - 1));
        int y = (int)fminf(fmaxf(py * SCALE, 0.f), (float)(Hn - 1));
        float* tg = g_target + (size_t)b * HWn;
        #pragma unroll
        for (int dy = -1; dy <= 1; ++dy) {
            int ny = y + dy;
            if ((unsigned)ny >= (unsigned)Hn) continue;
            #pragma unroll
            for (int dx = -1; dx <= 1; ++dx) {
                int nx = x + dx;
                if ((unsigned)nx < (unsigned)Wn) tg[ny * Wn + nx] = 0.f;
            }
        }
        return;
    }

    // finalize block (stream-ordered after K2; runs concurrent w/ clean, OK)
    double cnt = 0.0, sp = 0.0;
    if (tid < Bn) {
        double S = g_S[tid];
        cnt = fabs(S / CELL_AREA - (double)NPTS);
        double Sp = S + 1e-8;
        double T = g_T[tid];
        sp = (g_Q[tid] / (Sp * Sp) - 2.0 * g_A[tid] / (Sp * T) + g_C[tid] / (T * T))
             / (double)HWn;
        g_S[tid] = 0.0; g_Q[tid] = 0.0; g_T[tid] = 0.0;
        g_A[tid] = 0.0; g_C[tid] = 0.0;
    }
    #pragma unroll
    for (int o = 16; o; o >>= 1) {
        cnt += __shfl_down_sync(0xffffffffu, cnt, o);
        sp  += __shfl_down_sync(0xffffffffu, sp, o);
    }
    __shared__ double sc[2], ssp[2];
    int lane = tid & 31, wid = tid >> 5;
    if (wid < 2 && lane == 0) { sc[wid] = cnt; ssp[wid] = sp; }
    __syncthreads();
    if (tid == 0) {
        double count_loss = (sc[0] + sc[1]) / (double)Bn;
        double spatial    = (ssp[0] + ssp[1]) / (double)Bn;
        out[0] = (float)(2.5 * count_loss + 0.1 * spatial);
        out[1] = (float)count_loss;
        out[2] = (float)spatial;
    }
}

extern "C" void kernel_launch(void* const* d_in, const int* in_sizes, int n_in,
                              void* d_out, int out_size) {
    const float* pred   = (const float*)d_in[0];
    const float* points = (const float*)d_in[1];
    float* out = (float*)d_out;
    k_reduce<<<RB, 256>>>(pred);
    k_taps<<<TB, 256>>>(pred, points);
    k_tail<<<PB + 1, 256>>>(points, out);
}

// round 7
// speedup vs baseline: 10.5894x; 1.4460x over previous
#include <cuda_runtime.h>
#include <math.h>

constexpr int Bn   = 64;
constexpr int Hn   = 512;
constexpr int Wn   = 512;
constexpr int NPTS = 512;
constexpr int HWn  = Hn * Wn;
constexpr int SLICES = 16;                  // blocks per image
constexpr int RB = Bn * SLICES;             // 1024 blocks (single wave @occ7)
constexpr int TAPS_PER_IMG = NPTS * 9;      // 4608
constexpr int TAPS_PER_BLK = TAPS_PER_IMG / SLICES;   // 288
constexpr int PB = (Bn * NPTS) / 256;       // 128 cleanup blocks
constexpr float SCALE = 0.25f;              // 512/2048
constexpr double CELL_AREA = 16.0;

// zero-initialized device scratch; restored every call for graph replay
__device__ float  g_target[(size_t)Bn * HWn];
__device__ double g_S[Bn], g_Q[Bn], g_T[Bn], g_A[Bn], g_C[Bn];

// K1: each block streams its slice of pred (S,Q) then processes the 288 taps
//     of the same image chunk (scatter + T + A + C via atomic telescoping).
__global__ void __launch_bounds__(256, 7)
k_main(const float* __restrict__ pred, const float* __restrict__ points) {
    const int tid = threadIdx.x;
    const int b = blockIdx.x >> 4;
    const int slice = blockIdx.x & (SLICES - 1);

    // ---- streaming part: 16 float4 per thread, batched 8-deep ----
    constexpr int CH = HWn / 4 / SLICES;    // 4096 float4 per block
    const float4* p = reinterpret_cast<const float4*>(pred)
                      + (size_t)b * (HWn / 4) + (size_t)slice * CH;
    float s = 0.f, q = 0.f;
    #pragma unroll
    for (int it = 0; it < 2; ++it) {
        float4 v[8];
        #pragma unroll
        for (int j = 0; j < 8; ++j)
            v[j] = p[(it * 8 + j) * 256 + tid];
        #pragma unroll
        for (int j = 0; j < 8; ++j) {
            s += (v[j].x + v[j].y) + (v[j].z + v[j].w);
            q += v[j].x * v[j].x + v[j].y * v[j].y
               + v[j].z * v[j].z + v[j].w * v[j].w;
        }
    }

    // ---- tap part: 288 taps of image b, chunk 'slice' ----
    float tw = 0.f, ta = 0.f, tc = 0.f;
    const float* pb = pred + (size_t)b * HWn;
    float* tg = g_target + (size_t)b * HWn;
    for (int i = tid; i < TAPS_PER_BLK; i += 256) {
        int tapid = slice * TAPS_PER_BLK + i;    // < 4608
        int pt  = tapid / 9;
        int tap = tapid - pt * 9;
        float px = __ldg(&points[((size_t)b * NPTS + pt) * 2 + 0]);
        float py = __ldg(&points[((size_t)b * NPTS + pt) * 2 + 1]);
        int x = (int)fminf(fmaxf(px * SCALE, 0.f), (float)(Wn - 1));
        int y = (int)fminf(fmaxf(py * SCALE, 0.f), (float)(Hn - 1));
        int dy = tap / 3 - 1;
        int dx = tap - (tap / 3) * 3 - 1;
        int ny = y + dy, nx = x + dx;
        if ((unsigned)ny < (unsigned)Hn && (unsigned)nx < (unsigned)Wn) {
            int r2 = dy * dy + dx * dx;
            float w = (r2 == 0) ? 1.0f : (r2 == 1 ? 0.60653066f : 0.49306869f);
            int idx = ny * Wn + nx;
            float old = atomicAdd(&tg[idx], w);   // returning atomic
            tc += w * (2.f * old + w);            // (old+w)^2 - old^2
            ta += w * __ldg(&pb[idx]);            // L2-warm (image streaming now)
            tw += w;
        }
    }

    // ---- block reduce all five accumulators; whole block shares b ----
    #pragma unroll
    for (int o = 16; o; o >>= 1) {
        s  += __shfl_down_sync(0xffffffffu, s,  o);
        q  += __shfl_down_sync(0xffffffffu, q,  o);
        tw += __shfl_down_sync(0xffffffffu, tw, o);
        ta += __shfl_down_sync(0xffffffffu, ta, o);
        tc += __shfl_down_sync(0xffffffffu, tc, o);
    }
    __shared__ float sh[5][8];
    int lane = tid & 31, wid = tid >> 5;
    if (lane == 0) {
        sh[0][wid] = s; sh[1][wid] = q; sh[2][wid] = tw;
        sh[3][wid] = ta; sh[4][wid] = tc;
    }
    __syncthreads();
    if (wid == 0) {
        s  = (lane < 8) ? sh[0][lane] : 0.f;
        q  = (lane < 8) ? sh[1][lane] : 0.f;
        tw = (lane < 8) ? sh[2][lane] : 0.f;
        ta = (lane < 8) ? sh[3][lane] : 0.f;
        tc = (lane < 8) ? sh[4][lane] : 0.f;
        #pragma unroll
        for (int o = 4; o; o >>= 1) {
            s  += __shfl_down_sync(0xffffffffu, s,  o);
            q  += __shfl_down_sync(0xffffffffu, q,  o);
            tw += __shfl_down_sync(0xffffffffu, tw, o);
            ta += __shfl_down_sync(0xffffffffu, ta, o);
            tc += __shfl_down_sync(0xffffffffu, tc, o);
        }
        if (lane == 0) {
            atomicAdd(&g_S[b], (double)s);
            atomicAdd(&g_Q[b], (double)q);
            atomicAdd(&g_T[b], (double)tw);
            atomicAdd(&g_A[b], (double)ta);
            atomicAdd(&g_C[b], (double)tc);
        }
    }
}

// K2: blocks [0,PB) zero touched cells (plain stores); block PB finalizes.
__global__ void __launch_bounds__(256)
k_tail(const float* __restrict__ points, float* __restrict__ out) {
    const int tid = threadIdx.x;
    if (blockIdx.x < PB) {
        int pt = blockIdx.x * 256 + tid;
        int b = pt >> 9;
        float px = __ldg(&points[2 * pt + 0]);
        float py = __ldg(&points[2 * pt + 1]);
        int x = (int)fminf(fmaxf(px * SCALE, 0.f), (float)(Wn - 1));
        int y = (int)fminf(fmaxf(py * SCALE, 0.f), (float)(Hn - 1));
        float* tg = g_target + (size_t)b * HWn;
        #pragma unroll
        for (int dy = -1; dy <= 1; ++dy) {
            int ny = y + dy;
            if ((unsigned)ny >= (unsigned)Hn) continue;
            #pragma unroll
            for (int dx = -1; dx <= 1; ++dx) {
                int nx = x + dx;
                if ((unsigned)nx < (unsigned)Wn) tg[ny * Wn + nx] = 0.f;
            }
        }
        return;
    }

    // finalize (stream-ordered after K1)
    double cnt = 0.0, sp = 0.0;
    if (tid < Bn) {
        double S = g_S[tid];
        cnt = fabs(S / CELL_AREA - (double)NPTS);
        double Sp = S + 1e-8;
        double T = g_T[tid];
        sp = (g_Q[tid] / (Sp * Sp) - 2.0 * g_A[tid] / (Sp * T) + g_C[tid] / (T * T))
             / (double)HWn;
        g_S[tid] = 0.0; g_Q[tid] = 0.0; g_T[tid] = 0.0;
        g_A[tid] = 0.0; g_C[tid] = 0.0;
    }
    #pragma unroll
    for (int o = 16; o; o >>= 1) {
        cnt += __shfl_down_sync(0xffffffffu, cnt, o);
        sp  += __shfl_down_sync(0xffffffffu, sp, o);
    }
    __shared__ double sc[2], ssp[2];
    int lane = tid & 31, wid = tid >> 5;
    if (wid < 2 && lane == 0) { sc[wid] = cnt; ssp[wid] = sp; }
    __syncthreads();
    if (tid == 0) {
        double count_loss = (sc[0] + sc[1]) / (double)Bn;
        double spatial    = (ssp[0] + ssp[1]) / (double)Bn;
        out[0] = (float)(2.5 * count_loss + 0.1 * spatial);
        out[1] = (float)count_loss;
        out[2] = (float)spatial;
    }
}

extern "C" void kernel_launch(void* const* d_in, const int* in_sizes, int n_in,
                              void* d_out, int out_size) {
    const float* pred   = (const float*)d_in[0];
    const float* points = (const float*)d_in[1];
    float* out = (float*)d_out;
    k_main<<<RB, 256>>>(pred, points);
    k_tail<<<PB + 1, 256>>>(points, out);
}